// round 16
// baseline (speedup 1.0000x reference)
#include <cuda_runtime.h>
#include <cuda_fp16.h>
#include <math_constants.h>
#include <cstdint>

#define NMAX 50000
#define EMAX 800000

// ---------------- device scratch ----------------
__device__ __align__(16) float  g_h[NMAX * 128];
__device__ __align__(16) float  g_q[NMAX * 128];
__device__ __align__(16) __half g_kh[NMAX * 128];
__device__ __align__(16) __half g_vh[NMAX * 128];
__device__ __align__(16) float  g_skip[NMAX * 128];
__device__ __align__(16) float  g_h2[NMAX * 128];
__device__ __align__(16) float  g_qe[NMAX * 16];
__device__ __align__(16) __half g_wt[8 * 16384];   // pre-transposed fp16 W^T [n][k]
__device__ int   g_rowptr[NMAX + 1];
__device__ int   g_wp[NMAX + 1];
__device__ int   g_bsum[64];
__device__ int   g_ssrc[EMAX];
__device__ __align__(16) __half g_seah[EMAX * 16];
__device__ float g_red[4];                          // per-layer LN sums

__device__ __forceinline__ uint32_t s2u(const void* p) {
    uint32_t a;
    asm("{ .reg .u64 t; cvta.to.shared.u64 t, %1; cvt.u32.u64 %0, t; }" : "=r"(a) : "l"(p));
    return a;
}
__device__ __forceinline__ void cpa16(void* dst, const void* src) {
    asm volatile("cp.async.ca.shared.global [%0], [%1], 16;"
                 :: "r"(s2u(dst)), "l"(src) : "memory");
}
#define CP_COMMIT() asm volatile("cp.async.commit_group;" ::: "memory")
#define CP_WAIT(n)  asm volatile("cp.async.wait_group %0;" :: "n"(n) : "memory")

// load 8 consecutive halves (16B aligned) -> 8 floats
struct F8 { float v[8]; };
__device__ __forceinline__ F8 ldh8(const __half* p) {
    uint4 raw = *(const uint4*)p;
    F8 r;
    float2 f;
    f = __half22float2(*reinterpret_cast<__half2*>(&raw.x)); r.v[0] = f.x; r.v[1] = f.y;
    f = __half22float2(*reinterpret_cast<__half2*>(&raw.y)); r.v[2] = f.x; r.v[3] = f.y;
    f = __half22float2(*reinterpret_cast<__half2*>(&raw.z)); r.v[4] = f.x; r.v[5] = f.y;
    f = __half22float2(*reinterpret_cast<__half2*>(&raw.w)); r.v[6] = f.x; r.v[7] = f.y;
    return r;
}

// ---------------- W prep: transpose + fp16 into g_wt[m][n][k] ----------------
__global__ void k_prep4(const float* __restrict__ W0, const float* __restrict__ W1,
                        const float* __restrict__ W2, const float* __restrict__ W3,
                        int mbase) {
    int i = blockIdx.x * blockDim.x + threadIdx.x;
    if (i >= 4 * 16384) return;
    int m = i >> 14, j = i & 16383;
    const float* W = (m == 0) ? W0 : (m == 1) ? W1 : (m == 2) ? W2 : W3;
    int k = j >> 7, n = j & 127;
    g_wt[(mbase + m) * 16384 + n * 128 + k] = __float2half_rn(W[k * 128 + n]);
}

// ---------------- counting sort by dst ----------------
__global__ void k_zero_cnt(int n) {
    int i = blockIdx.x * blockDim.x + threadIdx.x;
    if (i <= n) g_wp[i] = 0;
}

__global__ void k_hist(const int* __restrict__ ei, int E) {
    int i = blockIdx.x * blockDim.x + threadIdx.x;
    if (i < E) atomicAdd(&g_wp[ei[E + i]], 1);
}

__global__ void k_scan1(int n) {
    __shared__ int sd[1024];
    int tid = threadIdx.x;
    int i = blockIdx.x * 1024 + tid;
    int v = (i < n) ? g_wp[i] : 0;
    sd[tid] = v;
    __syncthreads();
    for (int off = 1; off < 1024; off <<= 1) {
        int t = (tid >= off) ? sd[tid - off] : 0;
        __syncthreads();
        sd[tid] += t;
        __syncthreads();
    }
    if (i < n) g_rowptr[i] = sd[tid] - v;
    if (tid == 1023) g_bsum[blockIdx.x] = sd[1023];
}

__global__ void k_scan2(int nb) {
    if (threadIdx.x == 0) {
        int acc = 0;
        for (int b = 0; b < nb; b++) {
            int t = g_bsum[b];
            g_bsum[b] = acc;
            acc += t;
        }
        g_red[0] = 0.f; g_red[1] = 0.f; g_red[2] = 0.f; g_red[3] = 0.f;
    }
}

__global__ void k_scan3(int n, int E) {
    int i = blockIdx.x * blockDim.x + threadIdx.x;
    if (i < n) {
        int v = g_rowptr[i] + g_bsum[i >> 10];
        g_rowptr[i] = v;
        g_wp[i] = v;
    }
    if (i == n) g_rowptr[n] = E;
}

// scatter + fused ea permute (fp16)
__global__ void k_scatter(const int* __restrict__ ei, const float* __restrict__ ea, int E) {
    int i = blockIdx.x * blockDim.x + threadIdx.x;
    if (i < E) {
        int d = ei[E + i];
        int pos = atomicAdd(&g_wp[d], 1);
        g_ssrc[pos] = ei[i];
        const float4* src = (const float4*)(ea + (size_t)i * 16);
        __half2* dst = (__half2*)(g_seah + (size_t)pos * 16);
#pragma unroll
        for (int c = 0; c < 4; c++) {
            float4 v = src[c];
            dst[c * 2]     = __floats2half2_rn(v.x, v.y);
            dst[c * 2 + 1] = __floats2half2_rn(v.z, v.w);
        }
    }
}

// ---------------- fc1: h = x @ W1 + b1 ----------------
__global__ void k_fc1(const float* __restrict__ x, const float* __restrict__ W,
                      const float* __restrict__ b, int N) {
    __shared__ float xs[8 * 64];
    int j = threadIdx.x;            // 128 threads
    int r0 = blockIdx.x * 8;
    for (int t = j; t < 8 * 64; t += 128) {
        int r = t >> 6, k = t & 63;
        xs[t] = (r0 + r < N) ? x[(r0 + r) * 64 + k] : 0.f;
    }
    __syncthreads();
    float bj = b[j];
    float acc[8];
#pragma unroll
    for (int r = 0; r < 8; r++) acc[r] = bj;
    for (int k = 0; k < 64; k++) {
        float w = W[k * 128 + j];
#pragma unroll
        for (int r = 0; r < 8; r++) acc[r] += xs[r * 64 + k] * w;
    }
#pragma unroll
    for (int r = 0; r < 8; r++)
        if (r0 + r < N) g_h[(r0 + r) * 128 + j] = acc[r];
}

// ---------------- node transforms: fp16 mma, single-stage (all 4 B resident) ----
// 512 threads = 16 warps, warp tile 16x64. All 4 B matrices cp.async'd up front;
// one barrier total, then 4 compute+store phases with no intermediate syncs.
__global__ void __launch_bounds__(512, 1)
k_transform(int layer,
            const float* __restrict__ bq, const float* __restrict__ bk,
            const float* __restrict__ bv, const float* __restrict__ bs,
            int N) {
    __shared__ __half As[128][136];        // 34.8 KB
    __shared__ __half Bsh[4][128][136];    // 139.3 KB
    int tid = threadIdx.x, wid = tid >> 5, lane = tid & 31;
    int g = lane >> 2, tq = lane & 3;
    int r0 = blockIdx.x * 128;
    int rt = (wid & 7) * 16, ct = (wid >> 3) * 64;
    const __half* wt = g_wt + layer * 4 * 16384;
    const float* bm[4] = {bq, bk, bv, bs};

    // cp.async ALL FOUR B matrices (4 * 128 rows * 16 chunks of 16B)
#pragma unroll
    for (int it = 0; it < 16; it++) {
        int t = it * 512 + tid;
        int m = t >> 11, rest = t & 2047;
        int n = rest >> 4, c = rest & 15;
        cpa16(&Bsh[m][n][c * 8], wt + m * 16384 + n * 128 + c * 8);
    }
    CP_COMMIT();

    // stage A fp16
#pragma unroll
    for (int it = 0; it < 8; it++) {
        int i = it * 512 + tid;
        int r = i >> 5, q = i & 31;
        float4 v = (r0 + r < N) ? *(const float4*)(g_h + (r0 + r) * 128 + q * 4)
                                : make_float4(0.f, 0.f, 0.f, 0.f);
        __half2* d = (__half2*)&As[r][q * 4];
        d[0] = __floats2half2_rn(v.x, v.y);
        d[1] = __floats2half2_rn(v.z, v.w);
    }
    CP_WAIT(0);
    __syncthreads();    // the only barrier

#pragma unroll 1
    for (int m = 0; m < 4; m++) {
        float c4[8][4];
#pragma unroll
        for (int nt = 0; nt < 8; nt++) {
            c4[nt][0] = 0.f; c4[nt][1] = 0.f; c4[nt][2] = 0.f; c4[nt][3] = 0.f;
        }

#pragma unroll
        for (int ks = 0; ks < 8; ks++) {
            int k0 = ks * 16;
            uint32_t a0 = *(const uint32_t*)&As[rt + g][k0 + 2 * tq];
            uint32_t a1 = *(const uint32_t*)&As[rt + g + 8][k0 + 2 * tq];
            uint32_t a2 = *(const uint32_t*)&As[rt + g][k0 + 2 * tq + 8];
            uint32_t a3 = *(const uint32_t*)&As[rt + g + 8][k0 + 2 * tq + 8];
            uint32_t b0[8], b1[8];
#pragma unroll
            for (int nt = 0; nt < 8; nt++) {
                int col = ct + nt * 8 + g;
                b0[nt] = *(const uint32_t*)&Bsh[m][col][k0 + 2 * tq];
                b1[nt] = *(const uint32_t*)&Bsh[m][col][k0 + 2 * tq + 8];
            }
#pragma unroll
            for (int nt = 0; nt < 8; nt++) {
                asm volatile(
                    "mma.sync.aligned.m16n8k16.row.col.f32.f16.f16.f32 "
                    "{%0,%1,%2,%3}, {%4,%5,%6,%7}, {%8,%9}, {%0,%1,%2,%3};"
                    : "+f"(c4[nt][0]), "+f"(c4[nt][1]), "+f"(c4[nt][2]), "+f"(c4[nt][3])
                    : "r"(a0), "r"(a1), "r"(a2), "r"(a3),
                      "r"(b0[nt]), "r"(b1[nt]));
            }
        }

        const float* bb = bm[m];
        float* of = (m == 0) ? g_q : g_skip;
        __half* oh = (m == 1) ? g_kh : g_vh;
        bool is_half = (m == 1) || (m == 2);
        int row0 = r0 + rt + g;
        int row1 = row0 + 8;
#pragma unroll
        for (int nt = 0; nt < 8; nt++) {
            int col = ct + nt * 8 + tq * 2;
            float2 bj = *(const float2*)(bb + col);
            float v00 = c4[nt][0] + bj.x, v01 = c4[nt][1] + bj.y;
            float v10 = c4[nt][2] + bj.x, v11 = c4[nt][3] + bj.y;
            if (is_half) {
                if (row0 < N) *(__half2*)(oh + row0 * 128 + col) = __floats2half2_rn(v00, v01);
                if (row1 < N) *(__half2*)(oh + row1 * 128 + col) = __floats2half2_rn(v10, v11);
            } else {
                if (row0 < N) *(float2*)(of + row0 * 128 + col) = make_float2(v00, v01);
                if (row1 < N) *(float2*)(of + row1 * 128 + col) = make_float2(v10, v11);
            }
        }
    }
}

// ---------------- qe = q @ We^T ([N,16]) ----------------
__global__ void k_qe(const float* __restrict__ We, int N) {
    __shared__ float4 sWe4[512];
    int tid = threadIdx.x;               // 256 threads
    for (int t = tid; t < 512; t += 256) sWe4[t] = ((const float4*)We)[t];
    __syncthreads();
    int warp = tid >> 5, lane = tid & 31;
    int node = blockIdx.x * 8 + warp;
    if (node >= N) return;
    float4 q4 = *(const float4*)(g_q + node * 128 + lane * 4);
#pragma unroll
    for (int f = 0; f < 16; f++) {
        float4 w4 = sWe4[f * 32 + lane];
        float p = q4.x * w4.x;
        p = fmaf(q4.y, w4.y, p);
        p = fmaf(q4.z, w4.z, p);
        p = fmaf(q4.w, w4.w, p);
#pragma unroll
        for (int o = 16; o; o >>= 1) p += __shfl_xor_sync(0xffffffffu, p, o);
        if (lane == f) g_qe[node * 16 + f] = p;
    }
}

// ---------------- edge conv: 16 lanes/node, 4-edge unroll, gathers up front ------
__global__ void k_conv(const float* __restrict__ We, int N, int layer) {
    __shared__ float sWe[2048];
    __shared__ float rsum[8], rsum2[8];
    int tid = threadIdx.x;               // 256 threads = 8 warps = 16 nodes
    for (int t = tid; t < 2048; t += 256) sWe[t] = We[t];
    __syncthreads();
    int warp = tid >> 5, lane = tid & 31;
    int grp = lane >> 4, l16 = lane & 15;
    unsigned gmask = 0xFFFFu << (grp * 16);
    int node = blockIdx.x * 16 + warp * 2 + grp;

    float ls = 0.f, ls2 = 0.f;
    if (node < N) {
        const float RS = 0.08838834764831845f;   // 1/sqrt(128)
        int fb = l16 * 8;
        float4 qa = *(const float4*)(g_q + node * 128 + fb);
        float4 qb = *(const float4*)(g_q + node * 128 + fb + 4);
        float qef = g_qe[node * 16 + l16];
        int s0 = g_rowptr[node], s1 = g_rowptr[node + 1];

        float ssum = 0.f, wea = 0.f;
        float acc[8];
#pragma unroll
        for (int j = 0; j < 8; j++) acc[j] = 0.f;

        int e = s0;
        for (; e + 4 <= s1; e += 4) {
            int sA = g_ssrc[e],     sB = g_ssrc[e + 1];
            int sC = g_ssrc[e + 2], sD = g_ssrc[e + 3];
            F8 kA = ldh8(g_kh + sA * 128 + fb);
            F8 kB = ldh8(g_kh + sB * 128 + fb);
            F8 kC = ldh8(g_kh + sC * 128 + fb);
            F8 kD = ldh8(g_kh + sD * 128 + fb);
            F8 vA = ldh8(g_vh + sA * 128 + fb);
            F8 vB = ldh8(g_vh + sB * 128 + fb);
            F8 vC = ldh8(g_vh + sC * 128 + fb);
            F8 vD = ldh8(g_vh + sD * 128 + fb);
            float eaA = __half2float(g_seah[e * 16 + l16]);
            float eaB = __half2float(g_seah[(e + 1) * 16 + l16]);
            float eaC = __half2float(g_seah[(e + 2) * 16 + l16]);
            float eaD = __half2float(g_seah[(e + 3) * 16 + l16]);
            float dA = qef * eaA, dB = qef * eaB, dC = qef * eaC, dD = qef * eaD;
            const float* qf = &qa.x;   // qa/qb contiguous
#pragma unroll
            for (int j = 0; j < 4; j++) {
                dA = fmaf(qf[j], kA.v[j], dA); dB = fmaf(qf[j], kB.v[j], dB);
                dC = fmaf(qf[j], kC.v[j], dC); dD = fmaf(qf[j], kD.v[j], dD);
            }
            const float* qg = &qb.x;
#pragma unroll
            for (int j = 0; j < 4; j++) {
                dA = fmaf(qg[j], kA.v[j + 4], dA); dB = fmaf(qg[j], kB.v[j + 4], dB);
                dC = fmaf(qg[j], kC.v[j + 4], dC); dD = fmaf(qg[j], kD.v[j + 4], dD);
            }
#pragma unroll
            for (int o = 8; o; o >>= 1) {
                dA += __shfl_xor_sync(gmask, dA, o);
                dB += __shfl_xor_sync(gmask, dB, o);
                dC += __shfl_xor_sync(gmask, dC, o);
                dD += __shfl_xor_sync(gmask, dD, o);
            }
            float wA = __expf(dA * RS), wB = __expf(dB * RS);
            float wC = __expf(dC * RS), wD = __expf(dD * RS);
            ssum += (wA + wB) + (wC + wD);
            wea  += fmaf(wA, eaA, wB * eaB) + fmaf(wC, eaC, wD * eaD);
#pragma unroll
            for (int j = 0; j < 8; j++)
                acc[j] += fmaf(wA, vA.v[j], wB * vB.v[j])
                        + fmaf(wC, vC.v[j], wD * vD.v[j]);
        }
        for (; e < s1; e++) {
            int src = g_ssrc[e];
            F8 k8 = ldh8(g_kh + src * 128 + fb);
            F8 v8 = ldh8(g_vh + src * 128 + fb);
            float eav = __half2float(g_seah[e * 16 + l16]);
            float d = fmaf(qa.x, k8.v[0], qef * eav);
            d = fmaf(qa.y, k8.v[1], d);
            d = fmaf(qa.z, k8.v[2], d);
            d = fmaf(qa.w, k8.v[3], d);
            d = fmaf(qb.x, k8.v[4], d);
            d = fmaf(qb.y, k8.v[5], d);
            d = fmaf(qb.z, k8.v[6], d);
            d = fmaf(qb.w, k8.v[7], d);
#pragma unroll
            for (int o = 8; o; o >>= 1) d += __shfl_xor_sync(gmask, d, o);
            float w = __expf(d * RS);
            ssum += w;
            wea = fmaf(w, eav, wea);
#pragma unroll
            for (int j = 0; j < 8; j++) acc[j] = fmaf(w, v8.v[j], acc[j]);
        }

        float inv = 1.f / (ssum + 1e-16f);
        float ev[8];
#pragma unroll
        for (int j = 0; j < 8; j++) ev[j] = 0.f;
#pragma unroll
        for (int f = 0; f < 16; f++) {
            float wf = __shfl_sync(gmask, wea, grp * 16 + f);
            const float* wrow = &sWe[f * 128 + fb];
            float4 w0 = *(const float4*)(wrow);
            float4 w1 = *(const float4*)(wrow + 4);
            ev[0] = fmaf(wf, w0.x, ev[0]);
            ev[1] = fmaf(wf, w0.y, ev[1]);
            ev[2] = fmaf(wf, w0.z, ev[2]);
            ev[3] = fmaf(wf, w0.w, ev[3]);
            ev[4] = fmaf(wf, w1.x, ev[4]);
            ev[5] = fmaf(wf, w1.y, ev[5]);
            ev[6] = fmaf(wf, w1.z, ev[6]);
            ev[7] = fmaf(wf, w1.w, ev[7]);
        }
        float4 sk0 = *(const float4*)(g_skip + node * 128 + fb);
        float4 sk1 = *(const float4*)(g_skip + node * 128 + fb + 4);
        float4 o0, o1;
        o0.x = fmaf(acc[0] + ev[0], inv, sk0.x);
        o0.y = fmaf(acc[1] + ev[1], inv, sk0.y);
        o0.z = fmaf(acc[2] + ev[2], inv, sk0.z);
        o0.w = fmaf(acc[3] + ev[3], inv, sk0.w);
        o1.x = fmaf(acc[4] + ev[4], inv, sk1.x);
        o1.y = fmaf(acc[5] + ev[5], inv, sk1.y);
        o1.z = fmaf(acc[6] + ev[6], inv, sk1.z);
        o1.w = fmaf(acc[7] + ev[7], inv, sk1.w);
        *(float4*)(g_h2 + node * 128 + fb) = o0;
        *(float4*)(g_h2 + node * 128 + fb + 4) = o1;
        ls  = (o0.x + o0.y + o0.z + o0.w) + (o1.x + o1.y + o1.z + o1.w);
        ls2 = o0.x * o0.x + o0.y * o0.y + o0.z * o0.z + o0.w * o0.w
            + o1.x * o1.x + o1.y * o1.y + o1.z * o1.z + o1.w * o1.w;
    }
#pragma unroll
    for (int o = 16; o; o >>= 1) {
        ls  += __shfl_xor_sync(0xffffffffu, ls, o);
        ls2 += __shfl_xor_sync(0xffffffffu, ls2, o);
    }
    if (lane == 0) { rsum[warp] = ls; rsum2[warp] = ls2; }
    __syncthreads();
    if (warp == 0) {
        float s  = (lane < 8) ? rsum[lane] : 0.f;
        float s2 = (lane < 8) ? rsum2[lane] : 0.f;
#pragma unroll
        for (int o = 4; o; o >>= 1) {
            s  += __shfl_xor_sync(0xffffffffu, s, o);
            s2 += __shfl_xor_sync(0xffffffffu, s2, o);
        }
        if (lane == 0) {
            atomicAdd(&g_red[layer * 2], s);
            atomicAdd(&g_red[layer * 2 + 1], s2);
        }
    }
}

// ---------------- LN apply + ReLU (layer 1) ----------------
__global__ void k_lnapply(const float* __restrict__ w, const float* __restrict__ b, int N) {
    int i = blockIdx.x * blockDim.x + threadIdx.x;
    int total = N * 32;
    float inv = 1.f / (float)(N * 128);
    float mu  = g_red[0] * inv;
    float var = g_red[1] * inv - mu * mu;
    float rs  = rsqrtf(var + 1e-5f);
    if (i < total) {
        float4 v = ((const float4*)g_h2)[i];
        int d = i & 31;
        float4 wv = ((const float4*)w)[d];
        float4 bv = ((const float4*)b)[d];
        float4 o;
        o.x = fmaxf((v.x - mu) * rs * wv.x + bv.x, 0.f);
        o.y = fmaxf((v.y - mu) * rs * wv.y + bv.y, 0.f);
        o.z = fmaxf((v.z - mu) * rs * wv.z + bv.z, 0.f);
        o.w = fmaxf((v.w - mu) * rs * wv.w + bv.w, 0.f);
        ((float4*)g_h)[i] = o;
    }
}

// ---------------- LN apply + ReLU + fc2 (layer 2) ----------------
__global__ void k_ln_fc2(const float* __restrict__ lw, const float* __restrict__ lb,
                         const float* __restrict__ W, const float* __restrict__ b,
                         float* __restrict__ out, int N) {
    int tid = threadIdx.x, warp = tid >> 5, lane = tid & 31;
    int node = blockIdx.x * 8 + warp;
    if (node >= N) return;
    float inv = 1.f / (float)(N * 128);
    float mu  = g_red[2] * inv;
    float var = g_red[3] * inv - mu * mu;
    float rs  = rsqrtf(var + 1e-5f);
    float4 v = *(const float4*)(g_h2 + node * 128 + lane * 4);
    float4 wv = ((const float4*)lw)[lane];
    float4 bv = ((const float4*)lb)[lane];
    float4 fw = ((const float4*)W)[lane];
    float hx = fmaxf((v.x - mu) * rs * wv.x + bv.x, 0.f);
    float hy = fmaxf((v.y - mu) * rs * wv.y + bv.y, 0.f);
    float hz = fmaxf((v.z - mu) * rs * wv.z + bv.z, 0.f);
    float hw = fmaxf((v.w - mu) * rs * wv.w + bv.w, 0.f);
    float p = hx * fw.x;
    p = fmaf(hy, fw.y, p);
    p = fmaf(hz, fw.z, p);
    p = fmaf(hw, fw.w, p);
#pragma unroll
    for (int o = 16; o; o >>= 1) p += __shfl_xor_sync(0xffffffffu, p, o);
    if (lane == 0) out[node] = p + b[0];
}

// ---------------- launch ----------------
extern "C" void kernel_launch(void* const* d_in, const int* in_sizes, int n_in,
                              void* d_out, int out_size) {
    const float* x      = (const float*)d_in[0];
    const int*   ei     = (const int*)d_in[1];
    const float* ea     = (const float*)d_in[2];
    const float* fc1_w  = (const float*)d_in[3];
    const float* fc1_b  = (const float*)d_in[4];
    const float* fc2_w  = (const float*)d_in[27];
    const float* fc2_b  = (const float*)d_in[28];

    int N = in_sizes[0] / 64;
    int E = in_sizes[1] / 2;
    float* out = (float*)d_out;
    int nscan = (N + 1023) / 1024;
    int ngrid = (N + 127) / 128;

    // launch order keeps k_transform at slot #4 (the slot ncu profiles)
    k_fc1<<<(N + 7) / 8, 128>>>(x, fc1_w, fc1_b, N);                              // 1
    k_prep4<<<256, 256>>>((const float*)d_in[5], (const float*)d_in[7],
                          (const float*)d_in[9], (const float*)d_in[12], 0);      // 2
    k_prep4<<<256, 256>>>((const float*)d_in[16], (const float*)d_in[18],
                          (const float*)d_in[20], (const float*)d_in[23], 4);     // 3
    k_transform<<<ngrid, 512>>>(0, (const float*)d_in[6], (const float*)d_in[8],
                                (const float*)d_in[10], (const float*)d_in[13], N); // 4
    k_zero_cnt<<<(N + 256) / 256, 256>>>(N);                                      // 5
    k_hist<<<(E + 255) / 256, 256>>>(ei, E);                                      // 6
    k_scan1<<<nscan, 1024>>>(N);                                                  // 7
    k_scan2<<<1, 32>>>(nscan);                                                    // 8
    k_scan3<<<(N + 1 + 255) / 256, 256>>>(N, E);                                  // 9
    k_scatter<<<(E + 255) / 256, 256>>>(ei, ea, E);                               // 10

    // layer 1
    k_qe<<<(N + 7) / 8, 256>>>((const float*)d_in[11], N);
    k_conv<<<(N + 15) / 16, 256>>>((const float*)d_in[11], N, 0);
    k_lnapply<<<(N * 32 + 255) / 256, 256>>>((const float*)d_in[14], (const float*)d_in[15], N);

    // layer 2
    k_transform<<<ngrid, 512>>>(1, (const float*)d_in[17], (const float*)d_in[19],
                                (const float*)d_in[21], (const float*)d_in[24], N);
    k_qe<<<(N + 7) / 8, 256>>>((const float*)d_in[22], N);
    k_conv<<<(N + 15) / 16, 256>>>((const float*)d_in[22], N, 1);
    k_ln_fc2<<<(N + 7) / 8, 256>>>((const float*)d_in[25], (const float*)d_in[26],
                                   fc2_w, fc2_b, out, N);
}

// round 17
// speedup vs baseline: 1.0489x; 1.0489x over previous
#include <cuda_runtime.h>
#include <cuda_fp16.h>
#include <math_constants.h>
#include <cstdint>

#define NMAX 50000
#define EMAX 800000

// ---------------- device scratch ----------------
__device__ __align__(16) float  g_h[NMAX * 128];
__device__ __align__(16) float  g_q[NMAX * 128];
__device__ __align__(16) __half g_kvh[NMAX * 256];  // k (cols 0-127) | v (cols 128-255)
__device__ __align__(16) float  g_skip[NMAX * 128];
__device__ __align__(16) float  g_h2[NMAX * 128];
__device__ __align__(16) float  g_qe[NMAX * 16];
__device__ __align__(16) __half g_wt[8 * 16384];   // pre-transposed fp16 W^T [n][k]
__device__ int   g_rowptr[NMAX + 1];
__device__ int   g_wp[NMAX + 1];
__device__ int   g_bsum[64];
__device__ int   g_ssrc[EMAX];
__device__ __align__(16) __half g_seah[EMAX * 16];
__device__ float g_red[4];                          // per-layer LN sums

__device__ __forceinline__ uint32_t s2u(const void* p) {
    uint32_t a;
    asm("{ .reg .u64 t; cvta.to.shared.u64 t, %1; cvt.u32.u64 %0, t; }" : "=r"(a) : "l"(p));
    return a;
}
__device__ __forceinline__ void cpa16(void* dst, const void* src) {
    asm volatile("cp.async.ca.shared.global [%0], [%1], 16;"
                 :: "r"(s2u(dst)), "l"(src) : "memory");
}
#define CP_COMMIT() asm volatile("cp.async.commit_group;" ::: "memory")
#define CP_WAIT(n)  asm volatile("cp.async.wait_group %0;" :: "n"(n) : "memory")

// load 8 consecutive halves (16B aligned) -> 8 floats
struct F8 { float v[8]; };
__device__ __forceinline__ F8 ldh8(const __half* p) {
    uint4 raw = *(const uint4*)p;
    F8 r;
    float2 f;
    f = __half22float2(*reinterpret_cast<__half2*>(&raw.x)); r.v[0] = f.x; r.v[1] = f.y;
    f = __half22float2(*reinterpret_cast<__half2*>(&raw.y)); r.v[2] = f.x; r.v[3] = f.y;
    f = __half22float2(*reinterpret_cast<__half2*>(&raw.z)); r.v[4] = f.x; r.v[5] = f.y;
    f = __half22float2(*reinterpret_cast<__half2*>(&raw.w)); r.v[6] = f.x; r.v[7] = f.y;
    return r;
}

// ---------------- W prep: transpose + fp16 into g_wt[m][n][k] ----------------
__global__ void k_prep4(const float* __restrict__ W0, const float* __restrict__ W1,
                        const float* __restrict__ W2, const float* __restrict__ W3,
                        int mbase) {
    int i = blockIdx.x * blockDim.x + threadIdx.x;
    if (i >= 4 * 16384) return;
    int m = i >> 14, j = i & 16383;
    const float* W = (m == 0) ? W0 : (m == 1) ? W1 : (m == 2) ? W2 : W3;
    int k = j >> 7, n = j & 127;
    g_wt[(mbase + m) * 16384 + n * 128 + k] = __float2half_rn(W[k * 128 + n]);
}

// ---------------- counting sort by dst ----------------
__global__ void k_zero_cnt(int n) {
    int i = blockIdx.x * blockDim.x + threadIdx.x;
    if (i <= n) g_wp[i] = 0;
}

__global__ void k_hist(const int* __restrict__ ei, int E) {
    int i = blockIdx.x * blockDim.x + threadIdx.x;
    if (i < E) atomicAdd(&g_wp[ei[E + i]], 1);
}

__global__ void k_scan1(int n) {
    __shared__ int sd[1024];
    int tid = threadIdx.x;
    int i = blockIdx.x * 1024 + tid;
    int v = (i < n) ? g_wp[i] : 0;
    sd[tid] = v;
    __syncthreads();
    for (int off = 1; off < 1024; off <<= 1) {
        int t = (tid >= off) ? sd[tid - off] : 0;
        __syncthreads();
        sd[tid] += t;
        __syncthreads();
    }
    if (i < n) g_rowptr[i] = sd[tid] - v;
    if (tid == 1023) g_bsum[blockIdx.x] = sd[1023];
}

__global__ void k_scan2(int nb) {
    if (threadIdx.x == 0) {
        int acc = 0;
        for (int b = 0; b < nb; b++) {
            int t = g_bsum[b];
            g_bsum[b] = acc;
            acc += t;
        }
        g_red[0] = 0.f; g_red[1] = 0.f; g_red[2] = 0.f; g_red[3] = 0.f;
    }
}

__global__ void k_scan3(int n, int E) {
    int i = blockIdx.x * blockDim.x + threadIdx.x;
    if (i < n) {
        int v = g_rowptr[i] + g_bsum[i >> 10];
        g_rowptr[i] = v;
        g_wp[i] = v;
    }
    if (i == n) g_rowptr[n] = E;
}

// scatter + fused ea permute (fp16)
__global__ void k_scatter(const int* __restrict__ ei, const float* __restrict__ ea, int E) {
    int i = blockIdx.x * blockDim.x + threadIdx.x;
    if (i < E) {
        int d = ei[E + i];
        int pos = atomicAdd(&g_wp[d], 1);
        g_ssrc[pos] = ei[i];
        const float4* src = (const float4*)(ea + (size_t)i * 16);
        __half2* dst = (__half2*)(g_seah + (size_t)pos * 16);
#pragma unroll
        for (int c = 0; c < 4; c++) {
            float4 v = src[c];
            dst[c * 2]     = __floats2half2_rn(v.x, v.y);
            dst[c * 2 + 1] = __floats2half2_rn(v.z, v.w);
        }
    }
}

// ---------------- fc1: h = x @ W1 + b1 ----------------
__global__ void k_fc1(const float* __restrict__ x, const float* __restrict__ W,
                      const float* __restrict__ b, int N) {
    __shared__ float xs[8 * 64];
    int j = threadIdx.x;            // 128 threads
    int r0 = blockIdx.x * 8;
    for (int t = j; t < 8 * 64; t += 128) {
        int r = t >> 6, k = t & 63;
        xs[t] = (r0 + r < N) ? x[(r0 + r) * 64 + k] : 0.f;
    }
    __syncthreads();
    float bj = b[j];
    float acc[8];
#pragma unroll
    for (int r = 0; r < 8; r++) acc[r] = bj;
    for (int k = 0; k < 64; k++) {
        float w = W[k * 128 + j];
#pragma unroll
        for (int r = 0; r < 8; r++) acc[r] += xs[r * 64 + k] * w;
    }
#pragma unroll
    for (int r = 0; r < 8; r++)
        if (r0 + r < N) g_h[(r0 + r) * 128 + j] = acc[r];
}

// ---------------- node transforms: fp16 mma, single-stage (all 4 B resident) ----
// k -> g_kvh[:,0:128], v -> g_kvh[:,128:256] (interleaved rows for conv locality)
__global__ void __launch_bounds__(512, 1)
k_transform(int layer,
            const float* __restrict__ bq, const float* __restrict__ bk,
            const float* __restrict__ bv, const float* __restrict__ bs,
            int N) {
    __shared__ __half As[128][136];        // 34.8 KB
    __shared__ __half Bsh[4][128][136];    // 139.3 KB
    int tid = threadIdx.x, wid = tid >> 5, lane = tid & 31;
    int g = lane >> 2, tq = lane & 3;
    int r0 = blockIdx.x * 128;
    int rt = (wid & 7) * 16, ct = (wid >> 3) * 64;
    const __half* wt = g_wt + layer * 4 * 16384;
    const float* bm[4] = {bq, bk, bv, bs};

#pragma unroll
    for (int it = 0; it < 16; it++) {
        int t = it * 512 + tid;
        int m = t >> 11, rest = t & 2047;
        int n = rest >> 4, c = rest & 15;
        cpa16(&Bsh[m][n][c * 8], wt + m * 16384 + n * 128 + c * 8);
    }
    CP_COMMIT();

#pragma unroll
    for (int it = 0; it < 8; it++) {
        int i = it * 512 + tid;
        int r = i >> 5, q = i & 31;
        float4 v = (r0 + r < N) ? *(const float4*)(g_h + (r0 + r) * 128 + q * 4)
                                : make_float4(0.f, 0.f, 0.f, 0.f);
        __half2* d = (__half2*)&As[r][q * 4];
        d[0] = __floats2half2_rn(v.x, v.y);
        d[1] = __floats2half2_rn(v.z, v.w);
    }
    CP_WAIT(0);
    __syncthreads();

#pragma unroll 1
    for (int m = 0; m < 4; m++) {
        float c4[8][4];
#pragma unroll
        for (int nt = 0; nt < 8; nt++) {
            c4[nt][0] = 0.f; c4[nt][1] = 0.f; c4[nt][2] = 0.f; c4[nt][3] = 0.f;
        }

#pragma unroll
        for (int ks = 0; ks < 8; ks++) {
            int k0 = ks * 16;
            uint32_t a0 = *(const uint32_t*)&As[rt + g][k0 + 2 * tq];
            uint32_t a1 = *(const uint32_t*)&As[rt + g + 8][k0 + 2 * tq];
            uint32_t a2 = *(const uint32_t*)&As[rt + g][k0 + 2 * tq + 8];
            uint32_t a3 = *(const uint32_t*)&As[rt + g + 8][k0 + 2 * tq + 8];
            uint32_t b0[8], b1[8];
#pragma unroll
            for (int nt = 0; nt < 8; nt++) {
                int col = ct + nt * 8 + g;
                b0[nt] = *(const uint32_t*)&Bsh[m][col][k0 + 2 * tq];
                b1[nt] = *(const uint32_t*)&Bsh[m][col][k0 + 2 * tq + 8];
            }
#pragma unroll
            for (int nt = 0; nt < 8; nt++) {
                asm volatile(
                    "mma.sync.aligned.m16n8k16.row.col.f32.f16.f16.f32 "
                    "{%0,%1,%2,%3}, {%4,%5,%6,%7}, {%8,%9}, {%0,%1,%2,%3};"
                    : "+f"(c4[nt][0]), "+f"(c4[nt][1]), "+f"(c4[nt][2]), "+f"(c4[nt][3])
                    : "r"(a0), "r"(a1), "r"(a2), "r"(a3),
                      "r"(b0[nt]), "r"(b1[nt]));
            }
        }

        const float* bb = bm[m];
        int row0 = r0 + rt + g;
        int row1 = row0 + 8;
#pragma unroll
        for (int nt = 0; nt < 8; nt++) {
            int col = ct + nt * 8 + tq * 2;
            float2 bj = *(const float2*)(bb + col);
            float v00 = c4[nt][0] + bj.x, v01 = c4[nt][1] + bj.y;
            float v10 = c4[nt][2] + bj.x, v11 = c4[nt][3] + bj.y;
            if (m == 1 || m == 2) {
                int off = (m == 1) ? 0 : 128;        // k | v halves of g_kvh row
                if (row0 < N) *(__half2*)(g_kvh + row0 * 256 + off + col) = __floats2half2_rn(v00, v01);
                if (row1 < N) *(__half2*)(g_kvh + row1 * 256 + off + col) = __floats2half2_rn(v10, v11);
            } else {
                float* of = (m == 0) ? g_q : g_skip;
                if (row0 < N) *(float2*)(of + row0 * 128 + col) = make_float2(v00, v01);
                if (row1 < N) *(float2*)(of + row1 * 128 + col) = make_float2(v10, v11);
            }
        }
    }
}

// ---------------- qe = q @ We^T ([N,16]) ----------------
__global__ void k_qe(const float* __restrict__ We, int N) {
    __shared__ float4 sWe4[512];
    int tid = threadIdx.x;               // 256 threads
    for (int t = tid; t < 512; t += 256) sWe4[t] = ((const float4*)We)[t];
    __syncthreads();
    int warp = tid >> 5, lane = tid & 31;
    int node = blockIdx.x * 8 + warp;
    if (node >= N) return;
    float4 q4 = *(const float4*)(g_q + node * 128 + lane * 4);
#pragma unroll
    for (int f = 0; f < 16; f++) {
        float4 w4 = sWe4[f * 32 + lane];
        float p = q4.x * w4.x;
        p = fmaf(q4.y, w4.y, p);
        p = fmaf(q4.z, w4.z, p);
        p = fmaf(q4.w, w4.w, p);
#pragma unroll
        for (int o = 16; o; o >>= 1) p += __shfl_xor_sync(0xffffffffu, p, o);
        if (lane == f) g_qe[node * 16 + f] = p;
    }
}

// ---------------- edge conv: 16 lanes/node (2 nodes/warp), 2-edge unroll --------
__global__ void k_conv(const float* __restrict__ We, int N, int layer) {
    __shared__ float sWe[2048];
    __shared__ float rsum[8], rsum2[8];
    int tid = threadIdx.x;               // 256 threads = 8 warps = 16 nodes
    for (int t = tid; t < 2048; t += 256) sWe[t] = We[t];
    __syncthreads();
    int warp = tid >> 5, lane = tid & 31;
    int grp = lane >> 4, l16 = lane & 15;
    unsigned gmask = 0xFFFFu << (grp * 16);
    int node = blockIdx.x * 16 + warp * 2 + grp;

    float ls = 0.f, ls2 = 0.f;
    if (node < N) {
        const float RS = 0.08838834764831845f;   // 1/sqrt(128)
        int fb = l16 * 8;
        float4 qa = *(const float4*)(g_q + node * 128 + fb);
        float4 qb = *(const float4*)(g_q + node * 128 + fb + 4);
        float qef = g_qe[node * 16 + l16];
        int s0 = g_rowptr[node], s1 = g_rowptr[node + 1];

        float ssum = 0.f, wea = 0.f;
        float acc[8];
#pragma unroll
        for (int j = 0; j < 8; j++) acc[j] = 0.f;

        int e = s0;
        for (; e + 2 <= s1; e += 2) {
            int sA = g_ssrc[e], sB = g_ssrc[e + 1];
            const __half* rowA = g_kvh + (size_t)sA * 256 + fb;
            const __half* rowB = g_kvh + (size_t)sB * 256 + fb;
            F8 kA = ldh8(rowA);
            F8 kB = ldh8(rowB);
            F8 vA = ldh8(rowA + 128);
            F8 vB = ldh8(rowB + 128);
            float eaA = __half2float(g_seah[e * 16 + l16]);
            float eaB = __half2float(g_seah[(e + 1) * 16 + l16]);
            float dA = fmaf(qa.x, kA.v[0], qef * eaA);
            float dB = fmaf(qa.x, kB.v[0], qef * eaB);
            dA = fmaf(qa.y, kA.v[1], dA); dB = fmaf(qa.y, kB.v[1], dB);
            dA = fmaf(qa.z, kA.v[2], dA); dB = fmaf(qa.z, kB.v[2], dB);
            dA = fmaf(qa.w, kA.v[3], dA); dB = fmaf(qa.w, kB.v[3], dB);
            dA = fmaf(qb.x, kA.v[4], dA); dB = fmaf(qb.x, kB.v[4], dB);
            dA = fmaf(qb.y, kA.v[5], dA); dB = fmaf(qb.y, kB.v[5], dB);
            dA = fmaf(qb.z, kA.v[6], dA); dB = fmaf(qb.z, kB.v[6], dB);
            dA = fmaf(qb.w, kA.v[7], dA); dB = fmaf(qb.w, kB.v[7], dB);
#pragma unroll
            for (int o = 8; o; o >>= 1) {
                dA += __shfl_xor_sync(gmask, dA, o);
                dB += __shfl_xor_sync(gmask, dB, o);
            }
            float wA = __expf(dA * RS), wB = __expf(dB * RS);
            ssum += wA + wB;
            wea  += fmaf(wA, eaA, wB * eaB);
#pragma unroll
            for (int j = 0; j < 8; j++)
                acc[j] += fmaf(wA, vA.v[j], wB * vB.v[j]);
        }
        if (e < s1) {
            int src = g_ssrc[e];
            const __half* row = g_kvh + (size_t)src * 256 + fb;
            F8 k8 = ldh8(row);
            F8 v8 = ldh8(row + 128);
            float eav = __half2float(g_seah[e * 16 + l16]);
            float d = fmaf(qa.x, k8.v[0], qef * eav);
            d = fmaf(qa.y, k8.v[1], d);
            d = fmaf(qa.z, k8.v[2], d);
            d = fmaf(qa.w, k8.v[3], d);
            d = fmaf(qb.x, k8.v[4], d);
            d = fmaf(qb.y, k8.v[5], d);
            d = fmaf(qb.z, k8.v[6], d);
            d = fmaf(qb.w, k8.v[7], d);
#pragma unroll
            for (int o = 8; o; o >>= 1) d += __shfl_xor_sync(gmask, d, o);
            float w = __expf(d * RS);
            ssum += w;
            wea = fmaf(w, eav, wea);
#pragma unroll
            for (int j = 0; j < 8; j++) acc[j] = fmaf(w, v8.v[j], acc[j]);
        }

        float inv = 1.f / (ssum + 1e-16f);
        float ev[8];
#pragma unroll
        for (int j = 0; j < 8; j++) ev[j] = 0.f;
#pragma unroll
        for (int f = 0; f < 16; f++) {
            float wf = __shfl_sync(gmask, wea, grp * 16 + f);
            const float* wrow = &sWe[f * 128 + fb];
            float4 w0 = *(const float4*)(wrow);
            float4 w1 = *(const float4*)(wrow + 4);
            ev[0] = fmaf(wf, w0.x, ev[0]);
            ev[1] = fmaf(wf, w0.y, ev[1]);
            ev[2] = fmaf(wf, w0.z, ev[2]);
            ev[3] = fmaf(wf, w0.w, ev[3]);
            ev[4] = fmaf(wf, w1.x, ev[4]);
            ev[5] = fmaf(wf, w1.y, ev[5]);
            ev[6] = fmaf(wf, w1.z, ev[6]);
            ev[7] = fmaf(wf, w1.w, ev[7]);
        }
        float4 sk0 = *(const float4*)(g_skip + node * 128 + fb);
        float4 sk1 = *(const float4*)(g_skip + node * 128 + fb + 4);
        float4 o0, o1;
        o0.x = fmaf(acc[0] + ev[0], inv, sk0.x);
        o0.y = fmaf(acc[1] + ev[1], inv, sk0.y);
        o0.z = fmaf(acc[2] + ev[2], inv, sk0.z);
        o0.w = fmaf(acc[3] + ev[3], inv, sk0.w);
        o1.x = fmaf(acc[4] + ev[4], inv, sk1.x);
        o1.y = fmaf(acc[5] + ev[5], inv, sk1.y);
        o1.z = fmaf(acc[6] + ev[6], inv, sk1.z);
        o1.w = fmaf(acc[7] + ev[7], inv, sk1.w);
        *(float4*)(g_h2 + node * 128 + fb) = o0;
        *(float4*)(g_h2 + node * 128 + fb + 4) = o1;
        ls  = (o0.x + o0.y + o0.z + o0.w) + (o1.x + o1.y + o1.z + o1.w);
        ls2 = o0.x * o0.x + o0.y * o0.y + o0.z * o0.z + o0.w * o0.w
            + o1.x * o1.x + o1.y * o1.y + o1.z * o1.z + o1.w * o1.w;
    }
#pragma unroll
    for (int o = 16; o; o >>= 1) {
        ls  += __shfl_xor_sync(0xffffffffu, ls, o);
        ls2 += __shfl_xor_sync(0xffffffffu, ls2, o);
    }
    if (lane == 0) { rsum[warp] = ls; rsum2[warp] = ls2; }
    __syncthreads();
    if (warp == 0) {
        float s  = (lane < 8) ? rsum[lane] : 0.f;
        float s2 = (lane < 8) ? rsum2[lane] : 0.f;
#pragma unroll
        for (int o = 4; o; o >>= 1) {
            s  += __shfl_xor_sync(0xffffffffu, s, o);
            s2 += __shfl_xor_sync(0xffffffffu, s2, o);
        }
        if (lane == 0) {
            atomicAdd(&g_red[layer * 2], s);
            atomicAdd(&g_red[layer * 2 + 1], s2);
        }
    }
}

// ---------------- LN apply + ReLU (layer 1) ----------------
__global__ void k_lnapply(const float* __restrict__ w, const float* __restrict__ b, int N) {
    int i = blockIdx.x * blockDim.x + threadIdx.x;
    int total = N * 32;
    float inv = 1.f / (float)(N * 128);
    float mu  = g_red[0] * inv;
    float var = g_red[1] * inv - mu * mu;
    float rs  = rsqrtf(var + 1e-5f);
    if (i < total) {
        float4 v = ((const float4*)g_h2)[i];
        int d = i & 31;
        float4 wv = ((const float4*)w)[d];
        float4 bv = ((const float4*)b)[d];
        float4 o;
        o.x = fmaxf((v.x - mu) * rs * wv.x + bv.x, 0.f);
        o.y = fmaxf((v.y - mu) * rs * wv.y + bv.y, 0.f);
        o.z = fmaxf((v.z - mu) * rs * wv.z + bv.z, 0.f);
        o.w = fmaxf((v.w - mu) * rs * wv.w + bv.w, 0.f);
        ((float4*)g_h)[i] = o;
    }
}

// ---------------- LN apply + ReLU + fc2 (layer 2) ----------------
__global__ void k_ln_fc2(const float* __restrict__ lw, const float* __restrict__ lb,
                         const float* __restrict__ W, const float* __restrict__ b,
                         float* __restrict__ out, int N) {
    int tid = threadIdx.x, warp = tid >> 5, lane = tid & 31;
    int node = blockIdx.x * 8 + warp;
    if (node >= N) return;
    float inv = 1.f / (float)(N * 128);
    float mu  = g_red[2] * inv;
    float var = g_red[3] * inv - mu * mu;
    float rs  = rsqrtf(var + 1e-5f);
    float4 v = *(const float4*)(g_h2 + node * 128 + lane * 4);
    float4 wv = ((const float4*)lw)[lane];
    float4 bv = ((const float4*)lb)[lane];
    float4 fw = ((const float4*)W)[lane];
    float hx = fmaxf((v.x - mu) * rs * wv.x + bv.x, 0.f);
    float hy = fmaxf((v.y - mu) * rs * wv.y + bv.y, 0.f);
    float hz = fmaxf((v.z - mu) * rs * wv.z + bv.z, 0.f);
    float hw = fmaxf((v.w - mu) * rs * wv.w + bv.w, 0.f);
    float p = hx * fw.x;
    p = fmaf(hy, fw.y, p);
    p = fmaf(hz, fw.z, p);
    p = fmaf(hw, fw.w, p);
#pragma unroll
    for (int o = 16; o; o >>= 1) p += __shfl_xor_sync(0xffffffffu, p, o);
    if (lane == 0) out[node] = p + b[0];
}

// ---------------- launch ----------------
extern "C" void kernel_launch(void* const* d_in, const int* in_sizes, int n_in,
                              void* d_out, int out_size) {
    const float* x      = (const float*)d_in[0];
    const int*   ei     = (const int*)d_in[1];
    const float* ea     = (const float*)d_in[2];
    const float* fc1_w  = (const float*)d_in[3];
    const float* fc1_b  = (const float*)d_in[4];
    const float* fc2_w  = (const float*)d_in[27];
    const float* fc2_b  = (const float*)d_in[28];

    int N = in_sizes[0] / 64;
    int E = in_sizes[1] / 2;
    float* out = (float*)d_out;
    int nscan = (N + 1023) / 1024;
    int ngrid = (N + 127) / 128;

    // launch order keeps k_transform at slot #4 (the slot ncu profiles)
    k_fc1<<<(N + 7) / 8, 128>>>(x, fc1_w, fc1_b, N);                              // 1
    k_prep4<<<256, 256>>>((const float*)d_in[5], (const float*)d_in[7],
                          (const float*)d_in[9], (const float*)d_in[12], 0);      // 2
    k_prep4<<<256, 256>>>((const float*)d_in[16], (const float*)d_in[18],
                          (const float*)d_in[20], (const float*)d_in[23], 4);     // 3
    k_transform<<<ngrid, 512>>>(0, (const float*)d_in[6], (const float*)d_in[8],
                                (const float*)d_in[10], (const float*)d_in[13], N); // 4
    k_zero_cnt<<<(N + 256) / 256, 256>>>(N);                                      // 5
    k_hist<<<(E + 255) / 256, 256>>>(ei, E);                                      // 6
    k_scan1<<<nscan, 1024>>>(N);                                                  // 7
    k_scan2<<<1, 32>>>(nscan);                                                    // 8
    k_scan3<<<(N + 1 + 255) / 256, 256>>>(N, E);                                  // 9
    k_scatter<<<(E + 255) / 256, 256>>>(ei, ea, E);                               // 10

    // layer 1
    k_qe<<<(N + 7) / 8, 256>>>((const float*)d_in[11], N);
    k_conv<<<(N + 15) / 16, 256>>>((const float*)d_in[11], N, 0);
    k_lnapply<<<(N * 32 + 255) / 256, 256>>>((const float*)d_in[14], (const float*)d_in[15], N);

    // layer 2
    k_transform<<<ngrid, 512>>>(1, (const float*)d_in[17], (const float*)d_in[19],
                                (const float*)d_in[21], (const float*)d_in[24], N);
    k_qe<<<(N + 7) / 8, 256>>>((const float*)d_in[22], N);
    k_conv<<<(N + 15) / 16, 256>>>((const float*)d_in[22], N, 1);
    k_ln_fc2<<<(N + 7) / 8, 256>>>((const float*)d_in[25], (const float*)d_in[26],
                                   fc2_w, fc2_b, out, N);
}